// round 14
// baseline (speedup 1.0000x reference)
#include <cuda_runtime.h>
#include <math.h>

// Problem shape (fixed by reference)
#define BB 32
#define TT 2048
#define HE 1024
#define DEC_FLAT 2048

// 296 CTAs x 8 warps = 2368 warps = 32 batches x 74 warps, exactly.
// Every SM holds exactly 2 CTAs (one wave), every warp works.
#define GRID_MAIN 296
#define WPB 8
#define TW (GRID_MAIN * WPB)   // 2368 total warps
#define WPBATCH (TW / BB)      // 74 warps per batch

// Scratch: __device__ globals (no allocation allowed)
__device__ float g_ps[TW];
__device__ float g_pacc[(size_t)TW * HE];   // 9.25 MB
__device__ int   g_cnt[BB];                 // zero-init; reset by reducer

// ---------------------------------------------------------------------------
// Fully fused kernel (no online max: energies are bounded |e| < ~7 and a
// constant offset cancels exactly in the normalization, so plain exp is safe
// and partial combination is a pure sum):
//   phase 0: per-block cooperative bias for the 1-2 batches this block touches
//   phase 1: per-warp exp-weighted accumulation, TWO rows per iteration
//            (rows wb + k*74 within the warp's batch)
//   phase 2: CTA whose warps complete a batch (count hits 74) reduces it
// ---------------------------------------------------------------------------
__global__ __launch_bounds__(256, 2)
void attn_fused_kernel(const float* __restrict__ hidden,
                       const float* __restrict__ enc,
                       const float* __restrict__ mask,
                       const float* __restrict__ attn_w,
                       const float* __restrict__ attn_b,
                       float* __restrict__ out) {
    const int tid  = threadIdx.x;
    const int lane = tid & 31;
    const int wid  = tid >> 5;
    const int g    = blockIdx.x * WPB + wid;     // global warp id
    const int b    = g / WPBATCH;                // this warp's batch
    const int wb   = g % WPBATCH;                // warp index within batch
    const int b_lo = (blockIdx.x * WPB) / WPBATCH;
    const int b_hi = (blockIdx.x * WPB + WPB - 1) / WPBATCH;

    __shared__ float sh_we[HE];                  // w_e, shared per CTA (4 KB)
    __shared__ float sh[256];
    __shared__ float s_bias[2];
    __shared__ int   s_do[2];
    __shared__ float s_invS;

    // stage w_e into shared
    for (int j = tid; j < HE; j += 256) sh_we[j] = attn_w[DEC_FLAT + j];

    // ---- phase 0: biases for b_lo (threads 0-127) and b_hi (128-255) ----
    {
        const int ht = tid & 127;
        const int hb = (tid >> 7) ? b_hi : b_lo;
        float sum = 0.f;
        const float* h0 = hidden + (size_t)hb * HE;        // hidden[0, hb, :]
        const float* h1 = hidden + (size_t)(BB + hb) * HE; // hidden[1, hb, :]
#pragma unroll
        for (int j = ht; j < HE; j += 128)
            sum += h0[j] * attn_w[j] + h1[j] * attn_w[HE + j];
#pragma unroll
        for (int off = 16; off > 0; off >>= 1)
            sum += __shfl_xor_sync(0xffffffffu, sum, off);
        if (lane == 0) sh[wid] = sum;
        __syncthreads();
        if (tid == 0)   s_bias[0] = sh[0] + sh[1] + sh[2] + sh[3] + attn_b[0];
        if (tid == 128) s_bias[1] = sh[4] + sh[5] + sh[6] + sh[7] + attn_b[0];
        __syncthreads();
    }
    const float bias = s_bias[(b == b_lo) ? 0 : 1];

    // ---- phase 1: rows wb, wb+74, wb+148, ... two per iteration ----
    const int nrows = (TT - wb + WPBATCH - 1) / WPBATCH;   // 27 or 28
    // lane r holds mask for this warp's r-th row
    float mymask = 0.f;
    if (lane < nrows)
        mymask = mask[(size_t)b * TT + wb + (size_t)lane * WPBATCH];

    float4 av[8];
#pragma unroll
    for (int i = 0; i < 8; i++) av[i] = make_float4(0.f, 0.f, 0.f, 0.f);
    float s = 0.f;

    const float* encb = enc + (size_t)b * TT * HE;
    const float* wep  = sh_we + lane * 4;        // lane's float4 column base

    int k = 0;
    for (; k + 1 < nrows; k += 2) {
        const size_t row0 = (size_t)wb + (size_t)k * WPBATCH;
        const float4* p0 = (const float4*)(encb + row0 * HE);
        const float4* p1 = (const float4*)(encb + (row0 + WPBATCH) * HE);
        float4 rv0[8], rv1[8];
#pragma unroll
        for (int i = 0; i < 8; i++) rv0[i] = p0[i * 32 + lane];
#pragma unroll
        for (int i = 0; i < 8; i++) rv1[i] = p1[i * 32 + lane];  // MLP=16

        // two dots, 2 accumulators each (4-way ILP total); w_e from shared
        float e0a = 0.f, e0b = 0.f, e1a = 0.f, e1b = 0.f;
#pragma unroll
        for (int i = 0; i < 8; i += 2) {
            float4 w0 = *(const float4*)(wep + i * 128);
            float4 w1 = *(const float4*)(wep + (i + 1) * 128);
            e0a = fmaf(rv0[i].x, w0.x, e0a);
            e0a = fmaf(rv0[i].y, w0.y, e0a);
            e0a = fmaf(rv0[i].z, w0.z, e0a);
            e0a = fmaf(rv0[i].w, w0.w, e0a);
            e1a = fmaf(rv1[i].x, w0.x, e1a);
            e1a = fmaf(rv1[i].y, w0.y, e1a);
            e1a = fmaf(rv1[i].z, w0.z, e1a);
            e1a = fmaf(rv1[i].w, w0.w, e1a);
            e0b = fmaf(rv0[i + 1].x, w1.x, e0b);
            e0b = fmaf(rv0[i + 1].y, w1.y, e0b);
            e0b = fmaf(rv0[i + 1].z, w1.z, e0b);
            e0b = fmaf(rv0[i + 1].w, w1.w, e0b);
            e1b = fmaf(rv1[i + 1].x, w1.x, e1b);
            e1b = fmaf(rv1[i + 1].y, w1.y, e1b);
            e1b = fmaf(rv1[i + 1].z, w1.z, e1b);
            e1b = fmaf(rv1[i + 1].w, w1.w, e1b);
        }
        float e0 = e0a + e0b;
        float e1 = e1a + e1b;
        // interleaved butterfly reduces (ILP 2 on the shuffle chain)
#pragma unroll
        for (int off = 16; off > 0; off >>= 1) {
            e0 += __shfl_xor_sync(0xffffffffu, e0, off);
            e1 += __shfl_xor_sync(0xffffffffu, e1, off);
        }

        const float mk0 = __shfl_sync(0xffffffffu, mymask, k);
        const float mk1 = __shfl_sync(0xffffffffu, mymask, k + 1);
        const float pr0 = __expf((e0 + bias) * mk0) * mk0;
        const float pr1 = __expf((e1 + bias) * mk1) * mk1;
        s += pr0 + pr1;
#pragma unroll
        for (int i = 0; i < 8; i++) {
            av[i].x = fmaf(pr0, rv0[i].x, fmaf(pr1, rv1[i].x, av[i].x));
            av[i].y = fmaf(pr0, rv0[i].y, fmaf(pr1, rv1[i].y, av[i].y));
            av[i].z = fmaf(pr0, rv0[i].z, fmaf(pr1, rv1[i].z, av[i].z));
            av[i].w = fmaf(pr0, rv0[i].w, fmaf(pr1, rv1[i].w, av[i].w));
        }
    }
    if (k < nrows) {                         // odd tail row
        const size_t row0 = (size_t)wb + (size_t)k * WPBATCH;
        const float4* p0 = (const float4*)(encb + row0 * HE);
        float4 rv0[8];
#pragma unroll
        for (int i = 0; i < 8; i++) rv0[i] = p0[i * 32 + lane];
        float e0a = 0.f, e0b = 0.f;
#pragma unroll
        for (int i = 0; i < 8; i += 2) {
            float4 w0 = *(const float4*)(wep + i * 128);
            float4 w1 = *(const float4*)(wep + (i + 1) * 128);
            e0a = fmaf(rv0[i].x, w0.x, e0a);
            e0a = fmaf(rv0[i].y, w0.y, e0a);
            e0a = fmaf(rv0[i].z, w0.z, e0a);
            e0a = fmaf(rv0[i].w, w0.w, e0a);
            e0b = fmaf(rv0[i + 1].x, w1.x, e0b);
            e0b = fmaf(rv0[i + 1].y, w1.y, e0b);
            e0b = fmaf(rv0[i + 1].z, w1.z, e0b);
            e0b = fmaf(rv0[i + 1].w, w1.w, e0b);
        }
        float e0 = e0a + e0b;
#pragma unroll
        for (int off = 16; off > 0; off >>= 1)
            e0 += __shfl_xor_sync(0xffffffffu, e0, off);
        const float mk0 = __shfl_sync(0xffffffffu, mymask, k);
        const float pr0 = __expf((e0 + bias) * mk0) * mk0;
        s += pr0;
#pragma unroll
        for (int i = 0; i < 8; i++) {
            av[i].x = fmaf(pr0, rv0[i].x, av[i].x);
            av[i].y = fmaf(pr0, rv0[i].y, av[i].y);
            av[i].z = fmaf(pr0, rv0[i].z, av[i].z);
            av[i].w = fmaf(pr0, rv0[i].w, av[i].w);
        }
    }

    if (lane == 0) g_ps[g] = s;
    float4* outp = (float4*)(g_pacc + (size_t)g * HE);
#pragma unroll
    for (int i = 0; i < 8; i++) outp[i * 32 + lane] = av[i];

    // ---- phase 2: last CTA to complete a batch reduces its 74 partials ----
    __threadfence();                        // publish partials before arrival
    __syncthreads();                        // all warps' stores issued
    if (tid == 0) {
        const int cw0 = min((b_lo + 1) * WPBATCH, blockIdx.x * WPB + WPB)
                      - blockIdx.x * WPB;   // warps contributed to b_lo
        const int cw1 = WPB - cw0;          // warps contributed to b_hi
        s_do[0] = (atomicAdd(&g_cnt[b_lo], cw0) + cw0 == WPBATCH);
        s_do[1] = 0;
        if (cw1 > 0)
            s_do[1] = (atomicAdd(&g_cnt[b_hi], cw1) + cw1 == WPBATCH);
    }
    __syncthreads();

    for (int q = 0; q < 2; q++) {
        if (!s_do[q]) continue;
        const int rb = q ? b_hi : b_lo;
        __threadfence();                    // acquire side of the handoff

        // S = plain sum of the 74 partial sums
        float v = (tid < WPBATCH) ? g_ps[rb * WPBATCH + tid] : 0.f;
#pragma unroll
        for (int off = 16; off > 0; off >>= 1)
            v += __shfl_xor_sync(0xffffffffu, v, off);
        if (lane == 0) sh[wid] = v;
        __syncthreads();
        if (tid == 0) {
            float S = 0.f;
#pragma unroll
            for (int w = 0; w < WPB; w++) S += sh[w];
            s_invS = 1.f / S;
            g_cnt[rb] = 0;                  // reset for next graph replay
        }
        __syncthreads();
        const float inv = s_invS;

        // thread tid owns cols [tid*4, tid*4+4): pure sum over 74 partials
        float4 acc = make_float4(0.f, 0.f, 0.f, 0.f);
        const float* base = g_pacc + (size_t)rb * WPBATCH * HE + tid * 4;
#pragma unroll 2
        for (int p = 0; p < WPBATCH; p++) {
            float4 vv = *(const float4*)(base + (size_t)p * HE);
            acc.x += vv.x; acc.y += vv.y; acc.z += vv.z; acc.w += vv.w;
        }
        *(float4*)(out + (size_t)rb * HE + tid * 4) =
            make_float4(acc.x * inv, acc.y * inv, acc.z * inv, acc.w * inv);
        __syncthreads();                    // shared reuse safety across q
    }
}

// ---------------------------------------------------------------------------
// Entry point. Inputs (metadata order): hidden, encoder_outputs, mask,
// attn_w, attn_b. Output: (32, 1024) f32.
// ---------------------------------------------------------------------------
extern "C" void kernel_launch(void* const* d_in, const int* in_sizes, int n_in,
                              void* d_out, int out_size) {
    const float* hidden = (const float*)d_in[0];
    const float* enc    = (const float*)d_in[1];
    const float* mask   = (const float*)d_in[2];
    const float* attn_w = (const float*)d_in[3];
    const float* attn_b = (const float*)d_in[4];
    float* out = (float*)d_out;

    attn_fused_kernel<<<GRID_MAIN, 256>>>(hidden, enc, mask, attn_w, attn_b, out);
}